// round 2
// baseline (speedup 1.0000x reference)
#include <cuda_runtime.h>
#include <float.h>
#include <math.h>

#define BB 32
#define NN 24564
#define NC 21
#define TOPKK 200
#define NMSOUT 50
#define CONF_T 0.5f
#define IOU_T 0.45f
#define CAP 512            /* compaction capacity / sort width */
#define SORTN 512
#define STRIDE 24576       /* per-(b,c) candidate slot stride (>= NN) */
#define ROWS_PER_B (NC * NMSOUT) /* 1050 */

// Scratch (static device globals; no runtime allocation)
__device__ uint2  g_cand[(size_t)BB * NC * STRIDE]; // (score bits, anchor idx)
__device__ int    g_cnt[BB * NC];
__device__ float4 g_boxes[(size_t)BB * NN];
__device__ float  g_rows[(size_t)BB * ROWS_PER_B * 6];
__device__ float  g_sc[(size_t)BB * ROWS_PER_B];

// ---------------------------------------------------------------------------
// Kernel 0: zero the per-(b,c) candidate counters (graph replay safe)
// ---------------------------------------------------------------------------
__global__ void k_zero() {
    int i = blockIdx.x * blockDim.x + threadIdx.x;
    if (i < BB * NC) g_cnt[i] = 0;
}

// ---------------------------------------------------------------------------
// Kernel 1: decode boxes + warp-ballot compaction of candidates (> CONF_T)
// ---------------------------------------------------------------------------
__global__ __launch_bounds__(256) void k_decode(const float* __restrict__ pred) {
    __shared__ float stage[8][33 * 32];
    const int b = blockIdx.y;
    const int w = threadIdx.x >> 5, lane = threadIdx.x & 31;
    const int a0 = blockIdx.x * 256 + w * 32;

    const float* P = pred + (size_t)b * NN * 33;
    const long base = (long)a0 * 33;
#pragma unroll
    for (int k = 0; k < 33; k++) {
        long e = base + k * 32 + lane;
        stage[w][k * 32 + lane] = (e < (long)NN * 33) ? P[e] : 0.0f;
    }
    __syncwarp();

    const int a = a0 + lane;
    const bool act = (a < NN);
    const float* r = &stage[w][lane * 33];

    if (act) {
        float l0 = r[21], l1 = r[22], l2 = r[23], l3 = r[24];
        float ax = r[25], ay = r[26], aw = r[27], ah = r[28];
        float v0 = r[29], v1 = r[30], v2 = r[31], v3 = r[32];
        float cx = l0 * aw * v0 + ax;
        float cy = l1 * ah * v1 + ay;
        float wb = expf(l2 * v2) * aw;
        float hb = expf(l3 * v3) * ah;
        float xmin = (cx - 0.5f * wb) * 512.0f;
        float xmax = (cx + 0.5f * wb) * 512.0f;
        float ymin = (cy - 0.5f * hb) * 512.0f;
        float ymax = (cy + 0.5f * hb) * 512.0f;
        g_boxes[(size_t)b * NN + a] = make_float4(xmin, ymin, xmax, ymax);
    }

    // Per-class warp-ballot compaction into global candidate lists.
#pragma unroll
    for (int c = 0; c < NC; c++) {
        float s = act ? r[c] : 0.0f;
        bool pass = s > CONF_T;
        unsigned m = __ballot_sync(0xFFFFFFFFu, pass);
        int cnt = __popc(m);
        int posb = 0;
        if (lane == 0 && cnt) posb = atomicAdd(&g_cnt[b * NC + c], cnt);
        posb = __shfl_sync(0xFFFFFFFFu, posb, 0);
        if (pass) {
            int my = posb + __popc(m & ((1u << lane) - 1u));
            g_cand[(size_t)(b * NC + c) * STRIDE + my] =
                make_uint2(__float_as_uint(s), (unsigned)a);
        }
    }
}

// ---------------------------------------------------------------------------
// Kernel 2: per (b,c): radix-select 200th value, compact, sort, NMS via
//           precomputed IOU bit-matrix + single-thread greedy scan.
// ---------------------------------------------------------------------------
__global__ __launch_bounds__(256) void k_nms() {
    const int bc = blockIdx.x;
    const int b = bc / NC, c = bc % NC;
    const uint2* __restrict__ C = g_cand + (size_t)bc * STRIDE;
    const int tid = threadIdx.x;
    const int n = g_cnt[bc];

    __shared__ unsigned hist[256];
    __shared__ unsigned suf[257];
    __shared__ int s_p0, s_p01, sK, sDone;
    __shared__ unsigned sAbove, sFloor;
    __shared__ unsigned s_cnt;
    __shared__ float cs[SORTN];
    __shared__ int   ci[SORTN];
    __shared__ float4 bx[TOPKK];
    __shared__ unsigned sup[TOPKK][8];
    __shared__ int sel[NMSOUT];
    __shared__ unsigned char valf[NMSOUT];

    // ---- Phase A: radix-select threshold floor so that count(off>=floor)
    //      covers the top-200 and fits in CAP ----
    if (tid == 0) { sK = TOPKK; sAbove = 0u; sDone = 0; sFloor = 0u; s_p0 = -1; s_p01 = -1; }
    __syncthreads();

    if (n > CAP) {
        for (int lvl = 0; lvl < 3; lvl++) {
            if (sDone) break;
            const int nb = (lvl == 2) ? 128 : 256;
            for (int i = tid; i < nb; i += 256) hist[i] = 0u;
            __syncthreads();
            for (int i = tid; i < n; i += 256) {
                unsigned off = C[i].x - 0x3F000000u;
                if (off > 0x7FFFFFu) off = 0x7FFFFFu;
                int bin = -1;
                if (lvl == 0) bin = (int)(off >> 15);
                else if (lvl == 1) { if ((int)(off >> 15) == s_p0) bin = (int)((off >> 7) & 0xFFu); }
                else               { if ((int)(off >> 7)  == s_p01) bin = (int)(off & 0x7Fu); }
                if (bin >= 0) atomicAdd(&hist[bin], 1u);
            }
            __syncthreads();
            if (tid <= nb) {
                unsigned s = 0;
                for (int j = tid; j < nb; j++) s += hist[j];
                suf[tid] = s;
            }
            __syncthreads();
            const int Kl = sK;
            const unsigned Ab = sAbove;
            if (tid < nb) {
                if ((int)suf[tid] >= Kl && (int)suf[tid + 1] < Kl) {
                    unsigned total = Ab + suf[tid];
                    if (total <= (unsigned)CAP || lvl == 2) {
                        sDone = 1;
                        if (lvl == 0)      sFloor = ((unsigned)tid << 15);
                        else if (lvl == 1) sFloor = ((unsigned)s_p0 << 15) | ((unsigned)tid << 7);
                        else               sFloor = ((unsigned)s_p01 << 7) | (unsigned)tid;
                    } else {
                        if (lvl == 0) s_p0 = tid;
                        else          s_p01 = (s_p0 << 8) | tid;
                        sK = Kl - (int)suf[tid + 1];
                        sAbove = Ab + suf[tid + 1];
                    }
                }
            }
            __syncthreads();
        }
    }

    // ---- Phase B: compact entries with off >= floor into smem ----
    if (tid == 0) s_cnt = 0u;
    __syncthreads();
    const unsigned fl = (n > CAP) ? sFloor : 0u;
    for (int i = tid; i < n; i += 256) {
        uint2 e = C[i];
        unsigned off = e.x - 0x3F000000u;
        if (off > 0x7FFFFFu) off = 0x7FFFFFu;
        if (off >= fl) {
            unsigned p = atomicAdd(&s_cnt, 1u);
            if (p < (unsigned)SORTN) { cs[p] = __uint_as_float(e.x); ci[p] = (int)e.y; }
        }
    }
    __syncthreads();
    const unsigned csel = (s_cnt < (unsigned)SORTN) ? s_cnt : (unsigned)SORTN;
    for (int i = tid; i < SORTN; i += 256)
        if ((unsigned)i >= csel) { cs[i] = -FLT_MAX; ci[i] = 0x7FFFFFFF; }
    __syncthreads();

    // ---- Phase C: bitonic sort (score desc, idx asc) over SORTN ----
    for (int k = 2; k <= SORTN; k <<= 1) {
        for (int j = k >> 1; j > 0; j >>= 1) {
            for (int i = tid; i < SORTN; i += 256) {
                int x = i ^ j;
                if (x > i) {
                    float a = cs[i], d = cs[x];
                    int ia = ci[i], ib = ci[x];
                    bool a_first = (a > d) || (a == d && ia < ib);
                    bool up = ((i & k) == 0);
                    if (up != a_first) {
                        cs[i] = d; ci[i] = ib;
                        cs[x] = a; ci[x] = ia;
                    }
                }
            }
            __syncthreads();
        }
    }

    // ---- Phase D: gather top-200 boxes ----
    if (tid < TOPKK) {
        int id = ci[tid];
        bx[tid] = (id >= 0 && id < NN) ? g_boxes[(size_t)b * NN + id]
                                       : make_float4(0.f, 0.f, 0.f, 0.f);
    }
    __syncthreads();

    // ---- Phase E: IOU suppression bit-matrix (row t = pivot t) ----
    if (tid < TOPKK) {
        float4 p = bx[tid];
        float ap = (p.z - p.x) * (p.w - p.y);
        unsigned wbits[8] = {0, 0, 0, 0, 0, 0, 0, 0};
        for (int j = 0; j < TOPKK; j++) {
            float4 q = bx[j];
            float x1 = fmaxf(p.x, q.x), y1 = fmaxf(p.y, q.y);
            float x2 = fminf(p.z, q.z), y2 = fminf(p.w, q.w);
            float inter = fmaxf(x2 - x1, 0.0f) * fmaxf(y2 - y1, 0.0f);
            float aq = (q.z - q.x) * (q.w - q.y);
            float iou = inter / (ap + aq - inter + 1e-8f);
            if (iou > IOU_T) wbits[j >> 5] |= 1u << (j & 31);
        }
        wbits[tid >> 5] |= 1u << (tid & 31);  // self-suppression (idxr == i)
#pragma unroll
        for (int wdx = 0; wdx < 8; wdx++) sup[tid][wdx] = wbits[wdx];
    }
    __syncthreads();

    // ---- Phase F: greedy NMS scan (sorted order => first alive == argmax) ----
    const int A = (n < TOPKK) ? n : TOPKK;  // valid candidate count
    if (tid == 0) {
        unsigned al[7];
#pragma unroll
        for (int w2 = 0; w2 < 7; w2++) {
            int lo = w2 * 32;
            unsigned m = 0u;
            if (A >= lo + 32) m = 0xFFFFFFFFu;
            else if (A > lo)  m = (1u << (A - lo)) - 1u;
            al[w2] = m;
        }
        for (int k = 0; k < NMSOUT; k++) {
            int p = -1;
#pragma unroll
            for (int w2 = 0; w2 < 7; w2++)
                if (p < 0 && al[w2]) p = w2 * 32 + __ffs(al[w2]) - 1;
            if (p < 0) { sel[k] = 0; valf[k] = 0; }
            else {
                sel[k] = p; valf[k] = 1;
#pragma unroll
                for (int w2 = 0; w2 < 7; w2++) al[w2] &= ~sup[p][w2];
            }
        }
    }
    __syncthreads();

    // ---- Phase G: write rows + compact score column ----
    for (int e = tid; e < NMSOUT * 6; e += 256) {
        int r = e / 6, col = e % 6;
        float v = 0.0f;
        if (valf[r]) {
            int i = sel[r];
            if (col == 0)      v = (float)c;
            else if (col == 1) v = cs[i];
            else {
                float4 B2 = bx[i];
                v = (col == 2) ? B2.x : (col == 3) ? B2.y : (col == 4) ? B2.z : B2.w;
            }
        }
        g_rows[((size_t)bc * NMSOUT + r) * 6 + col] = v;
    }
    for (int r = tid; r < NMSOUT; r += 256)
        g_sc[(size_t)bc * NMSOUT + r] = valf[r] ? cs[sel[r]] : 0.0f;
}

// ---------------------------------------------------------------------------
// Kernel 3: per-batch top-200 of the 1050 rows (score desc, idx asc)
// ---------------------------------------------------------------------------
__global__ __launch_bounds__(512) void k_final(float* __restrict__ out) {
    __shared__ float ks[2048];
    __shared__ int   kid[2048];
    const int b = blockIdx.x;
    const int tid = threadIdx.x;

    for (int i = tid; i < 2048; i += 512) {
        if (i < ROWS_PER_B) {
            ks[i] = g_sc[(size_t)b * ROWS_PER_B + i];
            kid[i] = i;
        } else {
            ks[i] = -FLT_MAX;
            kid[i] = 0x7FFFFFFF;
        }
    }
    __syncthreads();

    for (int k = 2; k <= 2048; k <<= 1) {
        for (int j = k >> 1; j > 0; j >>= 1) {
            for (int i = tid; i < 2048; i += 512) {
                int x = i ^ j;
                if (x > i) {
                    float a = ks[i], d = ks[x];
                    int ia = kid[i], ib = kid[x];
                    bool a_first = (a > d) || (a == d && ia < ib);
                    bool up = ((i & k) == 0);
                    if (up != a_first) {
                        ks[i] = d; kid[i] = ib;
                        ks[x] = a; kid[x] = ia;
                    }
                }
            }
            __syncthreads();
        }
    }

    for (int e = tid; e < TOPKK * 6; e += 512) {
        int r = e / 6, col = e % 6;
        out[(size_t)b * TOPKK * 6 + e] =
            g_rows[((size_t)b * ROWS_PER_B + kid[r]) * 6 + col];
    }
}

extern "C" void kernel_launch(void* const* d_in, const int* in_sizes, int n_in,
                              void* d_out, int out_size) {
    const float* pred = (const float*)d_in[0];
    float* out = (float*)d_out;
    k_zero<<<3, 256>>>();
    dim3 g1((NN + 255) / 256, BB);
    k_decode<<<g1, 256>>>(pred);
    k_nms<<<BB * NC, 256>>>();
    k_final<<<BB, 512>>>(out);
}

// round 6
// speedup vs baseline: 1.2907x; 1.2907x over previous
#include <cuda_runtime.h>
#include <float.h>
#include <math.h>

#define BB 32
#define NN 24564
#define NC 21
#define TOPKK 200
#define NMSOUT 50
#define CONF_T 0.5f
#define IOU_T 0.45f
#define CAP 1024
#define ROWS_PER_B (NC * NMSOUT) /* 1050 */

// Scratch (static device globals; no runtime allocation)
__device__ float  g_scores[(size_t)BB * NC * NN];   // transposed conf (B, C, N)
__device__ float4 g_boxes[(size_t)BB * NN];          // decoded boxes
__device__ float  g_rows[(size_t)BB * ROWS_PER_B * 6];
__device__ float  g_sc[(size_t)BB * ROWS_PER_B];

// ---------------------------------------------------------------------------
// Kernel 1: decode boxes + transpose conf to (B, C, N)   [R1 verbatim]
// ---------------------------------------------------------------------------
__global__ __launch_bounds__(256) void k_decode(const float* __restrict__ pred) {
    __shared__ float stage[8][33 * 32];
    const int b = blockIdx.y;
    const int w = threadIdx.x >> 5, lane = threadIdx.x & 31;
    const int a0 = blockIdx.x * 256 + w * 32;

    const float* P = pred + (size_t)b * NN * 33;
    const long base = (long)a0 * 33;
#pragma unroll
    for (int k = 0; k < 33; k++) {
        long e = base + k * 32 + lane;
        stage[w][k * 32 + lane] = (e < (long)NN * 33) ? P[e] : 0.0f;
    }
    __syncwarp();

    const int a = a0 + lane;
    if (a < NN) {
        const float* r = &stage[w][lane * 33];
        float l0 = r[21], l1 = r[22], l2 = r[23], l3 = r[24];
        float ax = r[25], ay = r[26], aw = r[27], ah = r[28];
        float v0 = r[29], v1 = r[30], v2 = r[31], v3 = r[32];
        float cx = l0 * aw * v0 + ax;
        float cy = l1 * ah * v1 + ay;
        float wb = expf(l2 * v2) * aw;
        float hb = expf(l3 * v3) * ah;
        float xmin = (cx - 0.5f * wb) * 512.0f;
        float xmax = (cx + 0.5f * wb) * 512.0f;
        float ymin = (cy - 0.5f * hb) * 512.0f;
        float ymax = (cy + 0.5f * hb) * 512.0f;
        g_boxes[(size_t)b * NN + a] = make_float4(xmin, ymin, xmax, ymax);
#pragma unroll
        for (int c = 0; c < NC; c++)
            g_scores[((size_t)b * NC + c) * NN + a] = r[c];
    }
}

// ---------------------------------------------------------------------------
// Kernel 2: per (b,c): exact top-200 select (R1 Phase A/B/C verbatim) +
//           bit-matrix NMS (R2 proven) + row writes (R2 proven).
// ---------------------------------------------------------------------------
__global__ __launch_bounds__(256) void k_nms() {
    const int bc = blockIdx.x;
    const int b = bc / NC, c = bc % NC;
    const float* __restrict__ S = g_scores + ((size_t)b * NC + c) * NN;
    const int tid = threadIdx.x;

    __shared__ unsigned hist[256];
    __shared__ unsigned suf[257];
    __shared__ int s_bin, s_K, s_under;
    __shared__ unsigned s_cnt;
    __shared__ float cs[CAP];
    __shared__ int   ci[CAP];
    __shared__ float4 bx[TOPKK];
    __shared__ unsigned sup[TOPKK][8];
    __shared__ int sel[NMSOUT];
    __shared__ unsigned char valf[NMSOUT];

    // ---- Phase A: find the bit pattern of the 200th-largest masked score ----
    // scores in (0.5, 1.0): bits - 0x3F000000 spans (0, 2^23]. Three histogram
    // refinement passes: 8 bits, 8 bits, 7 bits.   [R1 verbatim + suf[nb]=0 fix]
    int K = TOPKK;
    unsigned prefix = 0;
    bool under = false;
    unsigned offstar = 1u;

    for (int pass = 0; pass < 3; pass++) {
        const int nb = (pass == 2) ? 128 : 256;
        for (int i = tid; i < 256; i += 256) hist[i] = 0u;
        __syncthreads();
        for (int n = tid; n < NN; n += 256) {
            float s = S[n];
            if (s > CONF_T) {
                unsigned off = __float_as_uint(s) - 0x3F000000u;
                if (off > 0x7FFFFFu) off = 0x7FFFFFu;
                if (pass == 0) {
                    atomicAdd(&hist[off >> 15], 1u);
                } else if (pass == 1) {
                    if ((off >> 15) == prefix) atomicAdd(&hist[(off >> 7) & 0xFFu], 1u);
                } else {
                    if ((off >> 7) == prefix) atomicAdd(&hist[off & 0x7Fu], 1u);
                }
            }
        }
        __syncthreads();
        // suffix sums: suf[i] = sum_{j>=i} hist[j]
        if (tid <= nb) {
            unsigned sum = 0;
            for (int j = tid; j < nb; j++) sum += hist[j];
            suf[tid] = sum;
        }
        if (tid == 0) suf[nb] = 0u;   // sum of empty tail (fixes uninit read)
        __syncthreads();
        if (pass == 0) {
            if (tid == 0) s_under = (suf[0] < (unsigned)K) ? 1 : 0;
            __syncthreads();
            if (s_under) { under = true; break; }  // fewer than 200 candidates
        }
        if (tid < nb) {
            if (suf[tid] >= (unsigned)K && suf[tid + 1] < (unsigned)K) {
                s_bin = tid;
                s_K = K - (int)suf[tid + 1];
            }
        }
        __syncthreads();
        if (pass == 0)      prefix = (unsigned)s_bin;
        else if (pass == 1) prefix = (prefix << 8) | (unsigned)s_bin;
        else                offstar = (prefix << 7) | (unsigned)s_bin;
        K = s_K;
        __syncthreads();
    }
    if (under) offstar = 1u;  // collect everything > CONF_T

    // ---- Phase B: compact all entries with score-bits >= offstar ----
    if (tid == 0) s_cnt = 0u;
    __syncthreads();
    for (int n = tid; n < NN; n += 256) {
        float s = S[n];
        if (s > CONF_T) {
            unsigned off = __float_as_uint(s) - 0x3F000000u;
            if (off > 0x7FFFFFu) off = 0x7FFFFFu;
            if (off >= offstar) {
                unsigned p = atomicAdd(&s_cnt, 1u);
                if (p < CAP) { cs[p] = s; ci[p] = n; }
            }
        }
    }
    __syncthreads();
    const unsigned cnt = (s_cnt < CAP) ? s_cnt : CAP;
    for (int i = tid; i < CAP; i += 256) {
        if ((unsigned)i >= cnt) { cs[i] = -FLT_MAX; ci[i] = 0x7FFFFFFF; }
    }
    __syncthreads();

    // ---- Phase C: bitonic sort (score desc, idx asc) over CAP entries ----
    for (int k = 2; k <= CAP; k <<= 1) {
        for (int j = k >> 1; j > 0; j >>= 1) {
            for (int i = tid; i < CAP; i += 256) {
                int x = i ^ j;
                if (x > i) {
                    float a = cs[i], d = cs[x];
                    int ia = ci[i], ib = ci[x];
                    bool a_first = (a > d) || (a == d && ia < ib);
                    bool up = ((i & k) == 0);
                    if (up != a_first) {
                        cs[i] = d; ci[i] = ib;
                        cs[x] = a; ci[x] = ia;
                    }
                }
            }
            __syncthreads();
        }
    }

    // ---- Phase D: gather top-200 boxes ----
    if (tid < TOPKK) {
        int id = ci[tid];
        bx[tid] = (id >= 0 && id < NN) ? g_boxes[(size_t)b * NN + id]
                                       : make_float4(0.f, 0.f, 0.f, 0.f);
    }
    __syncthreads();

    // ---- Phase E: IOU suppression bit-matrix (row t = pivot t)  [R2 proven] ----
    if (tid < TOPKK) {
        float4 p = bx[tid];
        float ap = (p.z - p.x) * (p.w - p.y);
        unsigned wbits[8] = {0, 0, 0, 0, 0, 0, 0, 0};
        for (int j = 0; j < TOPKK; j++) {
            float4 q = bx[j];
            float x1 = fmaxf(p.x, q.x), y1 = fmaxf(p.y, q.y);
            float x2 = fminf(p.z, q.z), y2 = fminf(p.w, q.w);
            float inter = fmaxf(x2 - x1, 0.0f) * fmaxf(y2 - y1, 0.0f);
            float aq = (q.z - q.x) * (q.w - q.y);
            float iou = inter / (ap + aq - inter + 1e-8f);
            if (iou > IOU_T) wbits[j >> 5] |= 1u << (j & 31);
        }
        wbits[tid >> 5] |= 1u << (tid & 31);  // self-suppression (idxr == i)
#pragma unroll
        for (int wdx = 0; wdx < 8; wdx++) sup[tid][wdx] = wbits[wdx];
    }
    __syncthreads();

    // ---- Phase F: greedy NMS scan (sorted => first alive == argmax) [R2] ----
    const int A = ((int)cnt < TOPKK) ? (int)cnt : TOPKK;
    if (tid == 0) {
        unsigned al[7];
#pragma unroll
        for (int w2 = 0; w2 < 7; w2++) {
            int lo = w2 * 32;
            unsigned m = 0u;
            if (A >= lo + 32) m = 0xFFFFFFFFu;
            else if (A > lo)  m = (1u << (A - lo)) - 1u;
            al[w2] = m;
        }
        for (int k = 0; k < NMSOUT; k++) {
            int p = -1;
#pragma unroll
            for (int w2 = 0; w2 < 7; w2++)
                if (p < 0 && al[w2]) p = w2 * 32 + __ffs(al[w2]) - 1;
            if (p < 0) { sel[k] = 0; valf[k] = 0; }
            else {
                sel[k] = p; valf[k] = 1;
#pragma unroll
                for (int w2 = 0; w2 < 7; w2++) al[w2] &= ~sup[p][w2];
            }
        }
    }
    __syncthreads();

    // ---- Phase G: write rows + compact score column  [R2 proven] ----
    for (int e = tid; e < NMSOUT * 6; e += 256) {
        int r = e / 6, col = e % 6;
        float v = 0.0f;
        if (valf[r]) {
            int i = sel[r];
            if (col == 0)      v = (float)c;
            else if (col == 1) v = cs[i];
            else {
                float4 B2 = bx[i];
                v = (col == 2) ? B2.x : (col == 3) ? B2.y : (col == 4) ? B2.z : B2.w;
            }
        }
        g_rows[((size_t)bc * NMSOUT + r) * 6 + col] = v;
    }
    for (int r = tid; r < NMSOUT; r += 256)
        g_sc[(size_t)bc * NMSOUT + r] = valf[r] ? cs[sel[r]] : 0.0f;
}

// ---------------------------------------------------------------------------
// Kernel 3: per-batch top-200 of the 1050 rows   [R2 verbatim, 512 threads]
// ---------------------------------------------------------------------------
__global__ __launch_bounds__(512) void k_final(float* __restrict__ out) {
    __shared__ float ks[2048];
    __shared__ int   kid[2048];
    const int b = blockIdx.x;
    const int tid = threadIdx.x;

    for (int i = tid; i < 2048; i += 512) {
        if (i < ROWS_PER_B) {
            ks[i] = g_sc[(size_t)b * ROWS_PER_B + i];
            kid[i] = i;
        } else {
            ks[i] = -FLT_MAX;
            kid[i] = 0x7FFFFFFF;
        }
    }
    __syncthreads();

    for (int k = 2; k <= 2048; k <<= 1) {
        for (int j = k >> 1; j > 0; j >>= 1) {
            for (int i = tid; i < 2048; i += 512) {
                int x = i ^ j;
                if (x > i) {
                    float a = ks[i], d = ks[x];
                    int ia = kid[i], ib = kid[x];
                    bool a_first = (a > d) || (a == d && ia < ib);
                    bool up = ((i & k) == 0);
                    if (up != a_first) {
                        ks[i] = d; kid[i] = ib;
                        ks[x] = a; kid[x] = ia;
                    }
                }
            }
            __syncthreads();
        }
    }

    for (int e = tid; e < TOPKK * 6; e += 512) {
        int r = e / 6, col = e % 6;
        out[(size_t)b * TOPKK * 6 + e] =
            g_rows[((size_t)b * ROWS_PER_B + kid[r]) * 6 + col];
    }
}

extern "C" void kernel_launch(void* const* d_in, const int* in_sizes, int n_in,
                              void* d_out, int out_size) {
    const float* pred = (const float*)d_in[0];
    float* out = (float*)d_out;
    dim3 g1((NN + 255) / 256, BB);
    k_decode<<<g1, 256>>>(pred);
    k_nms<<<BB * NC, 256>>>();
    k_final<<<BB, 512>>>(out);
}

// round 7
// speedup vs baseline: 2.3038x; 1.7849x over previous
#include <cuda_runtime.h>
#include <float.h>
#include <math.h>

#define BB 32
#define NN 24564
#define NC 21
#define TOPKK 200
#define NMSOUT 50
#define CONF_T 0.5f
#define IOU_T 0.45f
#define CAP 1024
#define ROWS_PER_B (NC * NMSOUT) /* 1050 */

// Scratch (static device globals; no runtime allocation)
__device__ float  g_scores[(size_t)BB * NC * NN];   // transposed conf (B, C, N)
__device__ float4 g_boxes[(size_t)BB * NN];          // decoded boxes
__device__ float  g_rows[(size_t)BB * ROWS_PER_B * 6];
__device__ float  g_sc[(size_t)BB * ROWS_PER_B];

// ---------------------------------------------------------------------------
// Kernel 1: decode boxes + transpose conf to (B, C, N)   [proven verbatim]
// ---------------------------------------------------------------------------
__global__ __launch_bounds__(256) void k_decode(const float* __restrict__ pred) {
    __shared__ float stage[8][33 * 32];
    const int b = blockIdx.y;
    const int w = threadIdx.x >> 5, lane = threadIdx.x & 31;
    const int a0 = blockIdx.x * 256 + w * 32;

    const float* P = pred + (size_t)b * NN * 33;
    const long base = (long)a0 * 33;
#pragma unroll
    for (int k = 0; k < 33; k++) {
        long e = base + k * 32 + lane;
        stage[w][k * 32 + lane] = (e < (long)NN * 33) ? P[e] : 0.0f;
    }
    __syncwarp();

    const int a = a0 + lane;
    if (a < NN) {
        const float* r = &stage[w][lane * 33];
        float l0 = r[21], l1 = r[22], l2 = r[23], l3 = r[24];
        float ax = r[25], ay = r[26], aw = r[27], ah = r[28];
        float v0 = r[29], v1 = r[30], v2 = r[31], v3 = r[32];
        float cx = l0 * aw * v0 + ax;
        float cy = l1 * ah * v1 + ay;
        float wb = expf(l2 * v2) * aw;
        float hb = expf(l3 * v3) * ah;
        float xmin = (cx - 0.5f * wb) * 512.0f;
        float xmax = (cx + 0.5f * wb) * 512.0f;
        float ymin = (cy - 0.5f * hb) * 512.0f;
        float ymax = (cy + 0.5f * hb) * 512.0f;
        g_boxes[(size_t)b * NN + a] = make_float4(xmin, ymin, xmax, ymax);
#pragma unroll
        for (int c = 0; c < NC; c++)
            g_scores[((size_t)b * NC + c) * NN + a] = r[c];
    }
}

// ---------------------------------------------------------------------------
// Kernel 2: per (b,c): histogram select w/ early exit, compact, dynamic-width
//           bitonic sort, alive-mask greedy NMS.
// ---------------------------------------------------------------------------
__global__ __launch_bounds__(256) void k_nms() {
    const int bc = blockIdx.x;
    const int b = bc / NC, c = bc % NC;
    const float* __restrict__ S = g_scores + ((size_t)b * NC + c) * NN;
    const int tid = threadIdx.x;

    __shared__ unsigned hist[256];
    __shared__ unsigned suf[257];
    __shared__ int s_bin, s_K, s_under, s_exit;
    __shared__ unsigned s_cnt;
    __shared__ float cs[CAP];
    __shared__ int   ci[CAP];
    __shared__ float4 bx[TOPKK];
    __shared__ unsigned alive[7];
    __shared__ int s_piv;
    __shared__ int sel[NMSOUT];
    __shared__ unsigned char valf[NMSOUT];

    // ---- Phase A: histogram refinement for the top-200 floor, with early
    //      exit once the collected superset fits in CAP (typ. 1 pass) ----
    int K = TOPKK;
    unsigned prefix = 0;
    bool under = false;
    unsigned offstar = 1u;

    for (int pass = 0; pass < 3; pass++) {
        const int nb = (pass == 2) ? 128 : 256;
        for (int i = tid; i < 256; i += 256) hist[i] = 0u;
        if (tid == 0) s_exit = 0;
        __syncthreads();
        for (int n = tid; n < NN; n += 256) {
            float s = S[n];
            if (s > CONF_T) {
                unsigned off = __float_as_uint(s) - 0x3F000000u;
                if (off > 0x7FFFFFu) off = 0x7FFFFFu;
                if (pass == 0) {
                    atomicAdd(&hist[off >> 15], 1u);
                } else if (pass == 1) {
                    if ((off >> 15) == prefix) atomicAdd(&hist[(off >> 7) & 0xFFu], 1u);
                } else {
                    if ((off >> 7) == prefix) atomicAdd(&hist[off & 0x7Fu], 1u);
                }
            }
        }
        __syncthreads();
        // suffix sums: suf[i] = sum_{j>=i} hist[j]
        if (tid <= nb) {
            unsigned sum = 0;
            for (int j = tid; j < nb; j++) sum += hist[j];
            suf[tid] = sum;
        }
        if (tid == 0) suf[nb] = 0u;
        __syncthreads();
        if (pass == 0) {
            if (tid == 0) s_under = (suf[0] < (unsigned)K) ? 1 : 0;
            __syncthreads();
            if (s_under) { under = true; break; }  // fewer than 200 candidates
        }
        if (tid < nb) {
            if (suf[tid] >= (unsigned)K && suf[tid + 1] < (unsigned)K) {
                s_bin = tid;
                s_K = K - (int)suf[tid + 1];
                // elements >= this bin's floor = (TOPKK - K) above-prefix + suf[tid]
                if ((unsigned)(TOPKK - K) + suf[tid] <= (unsigned)CAP) s_exit = 1;
            }
        }
        __syncthreads();
        if (s_exit) {
            // floor of the selected bin at this refinement level
            if (pass == 0)      offstar = ((unsigned)s_bin) << 15;
            else if (pass == 1) offstar = ((prefix << 8) | (unsigned)s_bin) << 7;
            else                offstar = (prefix << 7) | (unsigned)s_bin;
            break;
        }
        if (pass == 0)      prefix = (unsigned)s_bin;
        else if (pass == 1) prefix = (prefix << 8) | (unsigned)s_bin;
        else                offstar = (prefix << 7) | (unsigned)s_bin;
        K = s_K;
        __syncthreads();
    }
    if (under) offstar = 1u;  // collect everything > CONF_T

    // ---- Phase B: compact all entries with score-bits >= offstar ----
    if (tid == 0) s_cnt = 0u;
    __syncthreads();
    for (int n = tid; n < NN; n += 256) {
        float s = S[n];
        if (s > CONF_T) {
            unsigned off = __float_as_uint(s) - 0x3F000000u;
            if (off > 0x7FFFFFu) off = 0x7FFFFFu;
            if (off >= offstar) {
                unsigned p = atomicAdd(&s_cnt, 1u);
                if (p < CAP) { cs[p] = s; ci[p] = n; }
            }
        }
    }
    __syncthreads();
    const unsigned cnt = (s_cnt < CAP) ? s_cnt : CAP;
    for (int i = tid; i < CAP; i += 256) {
        if ((unsigned)i >= cnt) { cs[i] = -FLT_MAX; ci[i] = 0x7FFFFFFF; }
    }
    __syncthreads();

    // ---- Phase C: bitonic sort over SN = next_pow2(max(cnt,256)) ----
    int SN = 256;
    while (SN < (int)cnt) SN <<= 1;   // uniform across block (cnt from smem)
    for (int k = 2; k <= SN; k <<= 1) {
        for (int j = k >> 1; j > 0; j >>= 1) {
            for (int i = tid; i < SN; i += 256) {
                int x = i ^ j;
                if (x > i) {
                    float a = cs[i], d = cs[x];
                    int ia = ci[i], ib = ci[x];
                    bool a_first = (a > d) || (a == d && ia < ib);
                    bool up = ((i & k) == 0);
                    if (up != a_first) {
                        cs[i] = d; ci[i] = ib;
                        cs[x] = a; ci[x] = ia;
                    }
                }
            }
            __syncthreads();
        }
    }

    // ---- Phase D: gather top-200 boxes ----
    if (tid < TOPKK) {
        int id = ci[tid];
        bx[tid] = (id >= 0 && id < NN) ? g_boxes[(size_t)b * NN + id]
                                       : make_float4(0.f, 0.f, 0.f, 0.f);
    }
    const int A = ((int)cnt < TOPKK) ? (int)cnt : TOPKK;
    if (tid < 7) {
        int lo = tid * 32;
        unsigned m = 0u;
        if (A >= lo + 32) m = 0xFFFFFFFFu;
        else if (A > lo)  m = (1u << (A - lo)) - 1u;
        alive[tid] = m;
    }
    __syncthreads();

    // ---- Phase E: greedy NMS. Sorted order => argmax == first alive bit.
    //      Each alive word is read/written only by its own warp (no races). ----
    for (int k = 0; k < NMSOUT; k++) {
        if (tid == 0) {
            int p = -1;
#pragma unroll
            for (int w2 = 0; w2 < 7; w2++)
                if (p < 0 && alive[w2]) p = w2 * 32 + __ffs(alive[w2]) - 1;
            s_piv = p;
            if (p >= 0) {
                sel[k] = p; valf[k] = 1;
                alive[p >> 5] &= ~(1u << (p & 31));   // self-suppression
            } else {
                sel[k] = 0; valf[k] = 0;
            }
        }
        __syncthreads();
        const int p = s_piv;
        if (p >= 0) {
            bool supr = false;
            if (tid < A) {
                float4 pb = bx[p];
                float4 q = bx[tid];
                float x1 = fmaxf(pb.x, q.x), y1 = fmaxf(pb.y, q.y);
                float x2 = fminf(pb.z, q.z), y2 = fminf(pb.w, q.w);
                float inter = fmaxf(x2 - x1, 0.0f) * fmaxf(y2 - y1, 0.0f);
                float ap = (pb.z - pb.x) * (pb.w - pb.y);
                float aq = (q.z - q.x) * (q.w - q.y);
                float iou = inter / (ap + aq - inter + 1e-8f);
                supr = (iou > IOU_T);
            }
            unsigned m = __ballot_sync(0xFFFFFFFFu, supr);
            if ((tid & 31) == 0 && (tid >> 5) < 7 && m)
                alive[tid >> 5] &= ~m;
        }
        __syncthreads();
    }

    // ---- Phase F: write rows + compact score column  [proven verbatim] ----
    for (int e = tid; e < NMSOUT * 6; e += 256) {
        int r = e / 6, col = e % 6;
        float v = 0.0f;
        if (valf[r]) {
            int i = sel[r];
            if (col == 0)      v = (float)c;
            else if (col == 1) v = cs[i];
            else {
                float4 B2 = bx[i];
                v = (col == 2) ? B2.x : (col == 3) ? B2.y : (col == 4) ? B2.z : B2.w;
            }
        }
        g_rows[((size_t)bc * NMSOUT + r) * 6 + col] = v;
    }
    for (int r = tid; r < NMSOUT; r += 256)
        g_sc[(size_t)bc * NMSOUT + r] = valf[r] ? cs[sel[r]] : 0.0f;
}

// ---------------------------------------------------------------------------
// Kernel 3: per-batch top-200 of the 1050 rows   [proven verbatim, 512 thr]
// ---------------------------------------------------------------------------
__global__ __launch_bounds__(512) void k_final(float* __restrict__ out) {
    __shared__ float ks[2048];
    __shared__ int   kid[2048];
    const int b = blockIdx.x;
    const int tid = threadIdx.x;

    for (int i = tid; i < 2048; i += 512) {
        if (i < ROWS_PER_B) {
            ks[i] = g_sc[(size_t)b * ROWS_PER_B + i];
            kid[i] = i;
        } else {
            ks[i] = -FLT_MAX;
            kid[i] = 0x7FFFFFFF;
        }
    }
    __syncthreads();

    for (int k = 2; k <= 2048; k <<= 1) {
        for (int j = k >> 1; j > 0; j >>= 1) {
            for (int i = tid; i < 2048; i += 512) {
                int x = i ^ j;
                if (x > i) {
                    float a = ks[i], d = ks[x];
                    int ia = kid[i], ib = kid[x];
                    bool a_first = (a > d) || (a == d && ia < ib);
                    bool up = ((i & k) == 0);
                    if (up != a_first) {
                        ks[i] = d; kid[i] = ib;
                        ks[x] = a; kid[x] = ia;
                    }
                }
            }
            __syncthreads();
        }
    }

    for (int e = tid; e < TOPKK * 6; e += 512) {
        int r = e / 6, col = e % 6;
        out[(size_t)b * TOPKK * 6 + e] =
            g_rows[((size_t)b * ROWS_PER_B + kid[r]) * 6 + col];
    }
}

extern "C" void kernel_launch(void* const* d_in, const int* in_sizes, int n_in,
                              void* d_out, int out_size) {
    const float* pred = (const float*)d_in[0];
    float* out = (float*)d_out;
    dim3 g1((NN + 255) / 256, BB);
    k_decode<<<g1, 256>>>(pred);
    k_nms<<<BB * NC, 256>>>();
    k_final<<<BB, 512>>>(out);
}

// round 8
// speedup vs baseline: 2.6174x; 1.1361x over previous
#include <cuda_runtime.h>
#include <float.h>
#include <math.h>

#define BB 32
#define NN 24564
#define NC 21
#define TOPKK 200
#define NMSOUT 50
#define CONF_T 0.5f
#define IOU_T 0.45f
#define CAP 1024
#define FAST_FLOOR 0.98f
#define CAPF 256
#define ROWS_PER_B (NC * NMSOUT) /* 1050 */

// Scratch (static device globals; no runtime allocation)
__device__ float  g_scores[(size_t)BB * NC * NN];   // transposed conf (B, C, N)
__device__ float4 g_boxes[(size_t)BB * NN];          // decoded boxes
__device__ float  g_rows[(size_t)BB * ROWS_PER_B * 6];
__device__ float  g_sc[(size_t)BB * ROWS_PER_B];

// ---------------------------------------------------------------------------
// Kernel 1: decode boxes + transpose conf to (B, C, N)   [proven verbatim]
// ---------------------------------------------------------------------------
__global__ __launch_bounds__(256) void k_decode(const float* __restrict__ pred) {
    __shared__ float stage[8][33 * 32];
    const int b = blockIdx.y;
    const int w = threadIdx.x >> 5, lane = threadIdx.x & 31;
    const int a0 = blockIdx.x * 256 + w * 32;

    const float* P = pred + (size_t)b * NN * 33;
    const long base = (long)a0 * 33;
#pragma unroll
    for (int k = 0; k < 33; k++) {
        long e = base + k * 32 + lane;
        stage[w][k * 32 + lane] = (e < (long)NN * 33) ? P[e] : 0.0f;
    }
    __syncwarp();

    const int a = a0 + lane;
    if (a < NN) {
        const float* r = &stage[w][lane * 33];
        float l0 = r[21], l1 = r[22], l2 = r[23], l3 = r[24];
        float ax = r[25], ay = r[26], aw = r[27], ah = r[28];
        float v0 = r[29], v1 = r[30], v2 = r[31], v3 = r[32];
        float cx = l0 * aw * v0 + ax;
        float cy = l1 * ah * v1 + ay;
        float wb = expf(l2 * v2) * aw;
        float hb = expf(l3 * v3) * ah;
        float xmin = (cx - 0.5f * wb) * 512.0f;
        float xmax = (cx + 0.5f * wb) * 512.0f;
        float ymin = (cy - 0.5f * hb) * 512.0f;
        float ymax = (cy + 0.5f * hb) * 512.0f;
        g_boxes[(size_t)b * NN + a] = make_float4(xmin, ymin, xmax, ymax);
#pragma unroll
        for (int c = 0; c < NC; c++)
            g_scores[((size_t)b * NC + c) * NN + a] = r[c];
    }
}

// ---------------------------------------------------------------------------
// Kernel 2: per (b,c): fast fixed-floor compact (fallback: R6 histogram),
//           dynamic-width bitonic sort, alive-mask greedy NMS.
// ---------------------------------------------------------------------------
__global__ __launch_bounds__(256) void k_nms() {
    const int bc = blockIdx.x;
    const int b = bc / NC, c = bc % NC;
    const float* __restrict__ S = g_scores + ((size_t)b * NC + c) * NN;
    const int tid = threadIdx.x;

    __shared__ unsigned hist[256];
    __shared__ unsigned suf[257];
    __shared__ int s_bin, s_K, s_under, s_exit;
    __shared__ unsigned s_cnt;
    __shared__ float cs[CAP];
    __shared__ int   ci[CAP];
    __shared__ float4 bx[TOPKK];
    __shared__ unsigned alive[7];
    __shared__ int s_piv;
    __shared__ int sel[NMSOUT];
    __shared__ unsigned char valf[NMSOUT];

    // ---- FAST PATH: single compact pass with fixed floor ----
    if (tid == 0) s_cnt = 0u;
    __syncthreads();
    for (int n = tid; n < NN; n += 256) {
        float s = S[n];
        if (s > FAST_FLOOR) {
            unsigned p = atomicAdd(&s_cnt, 1u);
            if (p < CAP) { cs[p] = s; ci[p] = n; }
        }
    }
    __syncthreads();
    const unsigned fastcnt = s_cnt;
    const bool fast_ok = (fastcnt >= (unsigned)TOPKK) && (fastcnt <= (unsigned)CAP);

    if (!fast_ok) {
        // ---- FALLBACK Phase A: R6-proven histogram refinement w/ early exit ----
        int K = TOPKK;
        unsigned prefix = 0;
        bool under = false;
        unsigned offstar = 1u;

        for (int pass = 0; pass < 3; pass++) {
            const int nb = (pass == 2) ? 128 : 256;
            for (int i = tid; i < 256; i += 256) hist[i] = 0u;
            if (tid == 0) s_exit = 0;
            __syncthreads();
            for (int n = tid; n < NN; n += 256) {
                float s = S[n];
                if (s > CONF_T) {
                    unsigned off = __float_as_uint(s) - 0x3F000000u;
                    if (off > 0x7FFFFFu) off = 0x7FFFFFu;
                    if (pass == 0) {
                        atomicAdd(&hist[off >> 15], 1u);
                    } else if (pass == 1) {
                        if ((off >> 15) == prefix) atomicAdd(&hist[(off >> 7) & 0xFFu], 1u);
                    } else {
                        if ((off >> 7) == prefix) atomicAdd(&hist[off & 0x7Fu], 1u);
                    }
                }
            }
            __syncthreads();
            if (tid <= nb) {
                unsigned sum = 0;
                for (int j = tid; j < nb; j++) sum += hist[j];
                suf[tid] = sum;
            }
            if (tid == 0) suf[nb] = 0u;
            __syncthreads();
            if (pass == 0) {
                if (tid == 0) s_under = (suf[0] < (unsigned)K) ? 1 : 0;
                __syncthreads();
                if (s_under) { under = true; break; }
            }
            if (tid < nb) {
                if (suf[tid] >= (unsigned)K && suf[tid + 1] < (unsigned)K) {
                    s_bin = tid;
                    s_K = K - (int)suf[tid + 1];
                    if ((unsigned)(TOPKK - K) + suf[tid] <= (unsigned)CAP) s_exit = 1;
                }
            }
            __syncthreads();
            if (s_exit) {
                if (pass == 0)      offstar = ((unsigned)s_bin) << 15;
                else if (pass == 1) offstar = ((prefix << 8) | (unsigned)s_bin) << 7;
                else                offstar = (prefix << 7) | (unsigned)s_bin;
                break;
            }
            if (pass == 0)      prefix = (unsigned)s_bin;
            else if (pass == 1) prefix = (prefix << 8) | (unsigned)s_bin;
            else                offstar = (prefix << 7) | (unsigned)s_bin;
            K = s_K;
            __syncthreads();
        }
        if (under) offstar = 1u;

        // ---- FALLBACK Phase B: compact with offstar floor ----
        __syncthreads();
        if (tid == 0) s_cnt = 0u;
        __syncthreads();
        for (int n = tid; n < NN; n += 256) {
            float s = S[n];
            if (s > CONF_T) {
                unsigned off = __float_as_uint(s) - 0x3F000000u;
                if (off > 0x7FFFFFu) off = 0x7FFFFFu;
                if (off >= offstar) {
                    unsigned p = atomicAdd(&s_cnt, 1u);
                    if (p < CAP) { cs[p] = s; ci[p] = n; }
                }
            }
        }
        __syncthreads();
    }

    const unsigned cnt = (s_cnt < CAP) ? s_cnt : CAP;
    for (int i = tid; i < CAP; i += 256) {
        if ((unsigned)i >= cnt) { cs[i] = -FLT_MAX; ci[i] = 0x7FFFFFFF; }
    }
    __syncthreads();

    // ---- Phase C: bitonic sort over SN = next_pow2(max(cnt,256)) ----
    int SN = 256;
    while (SN < (int)cnt) SN <<= 1;
    for (int k = 2; k <= SN; k <<= 1) {
        for (int j = k >> 1; j > 0; j >>= 1) {
            for (int i = tid; i < SN; i += 256) {
                int x = i ^ j;
                if (x > i) {
                    float a = cs[i], d = cs[x];
                    int ia = ci[i], ib = ci[x];
                    bool a_first = (a > d) || (a == d && ia < ib);
                    bool up = ((i & k) == 0);
                    if (up != a_first) {
                        cs[i] = d; ci[i] = ib;
                        cs[x] = a; ci[x] = ia;
                    }
                }
            }
            __syncthreads();
        }
    }

    // ---- Phase D: gather top-200 boxes ----
    if (tid < TOPKK) {
        int id = ci[tid];
        bx[tid] = (id >= 0 && id < NN) ? g_boxes[(size_t)b * NN + id]
                                       : make_float4(0.f, 0.f, 0.f, 0.f);
    }
    const int A = ((int)cnt < TOPKK) ? (int)cnt : TOPKK;
    if (tid < 7) {
        int lo = tid * 32;
        unsigned m = 0u;
        if (A >= lo + 32) m = 0xFFFFFFFFu;
        else if (A > lo)  m = (1u << (A - lo)) - 1u;
        alive[tid] = m;
    }
    __syncthreads();

    // ---- Phase E: greedy NMS (proven verbatim) ----
    for (int k = 0; k < NMSOUT; k++) {
        if (tid == 0) {
            int p = -1;
#pragma unroll
            for (int w2 = 0; w2 < 7; w2++)
                if (p < 0 && alive[w2]) p = w2 * 32 + __ffs(alive[w2]) - 1;
            s_piv = p;
            if (p >= 0) {
                sel[k] = p; valf[k] = 1;
                alive[p >> 5] &= ~(1u << (p & 31));
            } else {
                sel[k] = 0; valf[k] = 0;
            }
        }
        __syncthreads();
        const int p = s_piv;
        if (p >= 0) {
            bool supr = false;
            if (tid < A) {
                float4 pb = bx[p];
                float4 q = bx[tid];
                float x1 = fmaxf(pb.x, q.x), y1 = fmaxf(pb.y, q.y);
                float x2 = fminf(pb.z, q.z), y2 = fminf(pb.w, q.w);
                float inter = fmaxf(x2 - x1, 0.0f) * fmaxf(y2 - y1, 0.0f);
                float ap = (pb.z - pb.x) * (pb.w - pb.y);
                float aq = (q.z - q.x) * (q.w - q.y);
                float iou = inter / (ap + aq - inter + 1e-8f);
                supr = (iou > IOU_T);
            }
            unsigned m = __ballot_sync(0xFFFFFFFFu, supr);
            if ((tid & 31) == 0 && (tid >> 5) < 7 && m)
                alive[tid >> 5] &= ~m;
        }
        __syncthreads();
    }

    // ---- Phase F: write rows + compact score column (proven verbatim) ----
    for (int e = tid; e < NMSOUT * 6; e += 256) {
        int r = e / 6, col = e % 6;
        float v = 0.0f;
        if (valf[r]) {
            int i = sel[r];
            if (col == 0)      v = (float)c;
            else if (col == 1) v = cs[i];
            else {
                float4 B2 = bx[i];
                v = (col == 2) ? B2.x : (col == 3) ? B2.y : (col == 4) ? B2.z : B2.w;
            }
        }
        g_rows[((size_t)bc * NMSOUT + r) * 6 + col] = v;
    }
    for (int r = tid; r < NMSOUT; r += 256)
        g_sc[(size_t)bc * NMSOUT + r] = valf[r] ? cs[sel[r]] : 0.0f;
}

// ---------------------------------------------------------------------------
// Kernel 3: per-batch top-200 of 1050 rows: radix-select a <=256 superset in
//           smem, bitonic-256, gather.  (Replaces the bitonic-2048.)
// ---------------------------------------------------------------------------
__global__ __launch_bounds__(256) void k_final(float* __restrict__ out) {
    const int b = blockIdx.x;
    const int tid = threadIdx.x;

    __shared__ float sc[ROWS_PER_B];
    __shared__ unsigned hist[256];
    __shared__ unsigned suf[257];
    __shared__ int s_bin, s_K, s_under, s_exit;
    __shared__ unsigned s_cnt;
    __shared__ float cs2[CAPF];
    __shared__ int   ci2[CAPF];

    for (int i = tid; i < ROWS_PER_B; i += 256)
        sc[i] = g_sc[(size_t)b * ROWS_PER_B + i];
    __syncthreads();

    // ---- Phase A: radix-select floor over the 1050 smem scores ----
    int K = TOPKK;
    unsigned prefix = 0;
    bool under = false;
    unsigned offstar = 1u;

    for (int pass = 0; pass < 3; pass++) {
        const int nb = (pass == 2) ? 128 : 256;
        for (int i = tid; i < 256; i += 256) hist[i] = 0u;
        if (tid == 0) s_exit = 0;
        __syncthreads();
        for (int n = tid; n < ROWS_PER_B; n += 256) {
            float s = sc[n];
            if (s > CONF_T) {
                unsigned off = __float_as_uint(s) - 0x3F000000u;
                if (off > 0x7FFFFFu) off = 0x7FFFFFu;
                if (pass == 0) {
                    atomicAdd(&hist[off >> 15], 1u);
                } else if (pass == 1) {
                    if ((off >> 15) == prefix) atomicAdd(&hist[(off >> 7) & 0xFFu], 1u);
                } else {
                    if ((off >> 7) == prefix) atomicAdd(&hist[off & 0x7Fu], 1u);
                }
            }
        }
        __syncthreads();
        if (tid <= nb) {
            unsigned sum = 0;
            for (int j = tid; j < nb; j++) sum += hist[j];
            suf[tid] = sum;
        }
        if (tid == 0) suf[nb] = 0u;
        __syncthreads();
        if (pass == 0) {
            if (tid == 0) s_under = (suf[0] < (unsigned)K) ? 1 : 0;
            __syncthreads();
            if (s_under) { under = true; break; }
        }
        if (tid < nb) {
            if (suf[tid] >= (unsigned)K && suf[tid + 1] < (unsigned)K) {
                s_bin = tid;
                s_K = K - (int)suf[tid + 1];
                if ((unsigned)(TOPKK - K) + suf[tid] <= (unsigned)CAPF) s_exit = 1;
            }
        }
        __syncthreads();
        if (s_exit) {
            if (pass == 0)      offstar = ((unsigned)s_bin) << 15;
            else if (pass == 1) offstar = ((prefix << 8) | (unsigned)s_bin) << 7;
            else                offstar = (prefix << 7) | (unsigned)s_bin;
            break;
        }
        if (pass == 0)      prefix = (unsigned)s_bin;
        else if (pass == 1) prefix = (prefix << 8) | (unsigned)s_bin;
        else                offstar = (prefix << 7) | (unsigned)s_bin;
        K = s_K;
        __syncthreads();
    }
    if (under) offstar = 1u;

    // ---- Phase B: compact rows with off >= floor ----
    if (tid == 0) s_cnt = 0u;
    __syncthreads();
    for (int n = tid; n < ROWS_PER_B; n += 256) {
        float s = sc[n];
        if (s > CONF_T) {
            unsigned off = __float_as_uint(s) - 0x3F000000u;
            if (off > 0x7FFFFFu) off = 0x7FFFFFu;
            if (off >= offstar) {
                unsigned p = atomicAdd(&s_cnt, 1u);
                if (p < (unsigned)CAPF) { cs2[p] = s; ci2[p] = n; }
            }
        }
    }
    __syncthreads();
    // Under-200 fill: append lowest-index zero rows (never taken w/ this data)
    if (tid == 0 && s_cnt < (unsigned)TOPKK) {
        unsigned k2 = s_cnt;
        for (int n = 0; n < ROWS_PER_B && k2 < (unsigned)TOPKK; n++) {
            if (!(sc[n] > CONF_T)) { cs2[k2] = sc[n]; ci2[k2] = n; k2++; }
        }
        s_cnt = k2;
    }
    __syncthreads();
    const unsigned cnt = (s_cnt < (unsigned)CAPF) ? s_cnt : (unsigned)CAPF;
    for (int i = tid; i < CAPF; i += 256)
        if ((unsigned)i >= cnt) { cs2[i] = -FLT_MAX; ci2[i] = 0x7FFFFFFF; }
    __syncthreads();

    // ---- Phase C: bitonic sort over CAPF=256 (score desc, idx asc) ----
    for (int k = 2; k <= CAPF; k <<= 1) {
        for (int j = k >> 1; j > 0; j >>= 1) {
            for (int i = tid; i < CAPF; i += 256) {
                int x = i ^ j;
                if (x > i) {
                    float a = cs2[i], d = cs2[x];
                    int ia = ci2[i], ib = ci2[x];
                    bool a_first = (a > d) || (a == d && ia < ib);
                    bool up = ((i & k) == 0);
                    if (up != a_first) {
                        cs2[i] = d; ci2[i] = ib;
                        cs2[x] = a; ci2[x] = ia;
                    }
                }
            }
            __syncthreads();
        }
    }

    // ---- Phase D: gather output rows ----
    for (int e = tid; e < TOPKK * 6; e += 256) {
        int r = e / 6, col = e % 6;
        int src = ci2[r];
        if (src < 0 || src >= ROWS_PER_B) src = 0;   // safety clamp
        out[(size_t)b * TOPKK * 6 + e] =
            g_rows[((size_t)b * ROWS_PER_B + src) * 6 + col];
    }
}

extern "C" void kernel_launch(void* const* d_in, const int* in_sizes, int n_in,
                              void* d_out, int out_size) {
    const float* pred = (const float*)d_in[0];
    float* out = (float*)d_out;
    dim3 g1((NN + 255) / 256, BB);
    k_decode<<<g1, 256>>>(pred);
    k_nms<<<BB * NC, 256>>>();
    k_final<<<BB, 256>>>(out);
}